// round 1
// baseline (speedup 1.0000x reference)
#include <cuda_runtime.h>
#include <math.h>

// ---------------------------------------------------------------------------
// Problem dimensions (fixed by the reference)
// ---------------------------------------------------------------------------
#define SQ   2048   // sequence length (q and kv)
#define HDIM 1024   // hidden size
#define NH   16     // num heads
#define HD   64     // head dim
#define ISZ  4096   // intermediate size

// ---------------------------------------------------------------------------
// Scratch (device-global arrays: allocation-free per harness rules)
// ---------------------------------------------------------------------------
__device__ float g_xn [SQ * HDIM];   // normalized activations
__device__ float g_q  [SQ * HDIM];
__device__ float g_k  [SQ * HDIM];
__device__ float g_v  [SQ * HDIM];
__device__ float g_att[SQ * HDIM];   // attention output (pre o-proj)
__device__ float g_h1 [SQ * HDIM];   // after self-attention block
__device__ float g_h2 [SQ * HDIM];   // after cross-attention block
__device__ float g_gate[SQ * ISZ];
__device__ float g_up  [SQ * ISZ];
__device__ float g_gu  [SQ * ISZ];

// ---------------------------------------------------------------------------
// RMSNorm: one block per row, 256 threads, H=1024 -> one float4 per thread
// ---------------------------------------------------------------------------
__global__ void __launch_bounds__(256) rmsnorm_kernel(
    const float* __restrict__ x, const float* __restrict__ w,
    float* __restrict__ y)
{
    const int row = blockIdx.x;
    const int t   = threadIdx.x;
    float4 vx = ((const float4*)(x + (size_t)row * HDIM))[t];
    float s = vx.x*vx.x + vx.y*vx.y + vx.z*vx.z + vx.w*vx.w;
    #pragma unroll
    for (int o = 16; o; o >>= 1) s += __shfl_xor_sync(0xffffffffu, s, o);

    __shared__ float red[8];
    __shared__ float s_inv;
    if ((t & 31) == 0) red[t >> 5] = s;
    __syncthreads();
    if (t == 0) {
        float tot = 0.f;
        #pragma unroll
        for (int i = 0; i < 8; ++i) tot += red[i];
        s_inv = 1.0f / sqrtf(tot * (1.0f / (float)HDIM) + 1e-6f);
    }
    __syncthreads();
    const float r = s_inv;
    float4 vw = ((const float4*)w)[t];
    float4 o4 = make_float4(vx.x*r*vw.x, vx.y*r*vw.y, vx.z*r*vw.z, vx.w*r*vw.w);
    ((float4*)(y + (size_t)row * HDIM))[t] = o4;
}

// ---------------------------------------------------------------------------
// SGEMM: C[M,N] = A[M,K] @ B[K,N] (+ R), all row-major.
// 128x128 block tile, BK=16, 256 threads, 8x8 per thread (split 2x(4) rows,
// 2x(4) cols for conflict-free float4 shared loads).
// ---------------------------------------------------------------------------
#define BM 128
#define BN 128
#define BK 16

__global__ void __launch_bounds__(256) sgemm_kernel(
    const float* __restrict__ A, const float* __restrict__ B,
    const float* __restrict__ R, float* __restrict__ C,
    int M, int N, int K)
{
    __shared__ float As[BK][BM + 4];   // transposed A tile, padded
    __shared__ float Bs[BK][BN];       // natural B tile

    const int tid = threadIdx.x;
    const int ty  = tid >> 4;          // 0..15 (row group)
    const int tx  = tid & 15;          // 0..15 (col group)
    const int bm  = blockIdx.y * BM;
    const int bn  = blockIdx.x * BN;

    float acc[2][2][4][4] = {};        // [rh][ch][e][f]

    for (int k0 = 0; k0 < K; k0 += BK) {
        // Load A tile (128x16): 2 float4 per thread
        #pragma unroll
        for (int it = 0; it < 2; ++it) {
            const int ar = (tid >> 2) + it * 64;
            const int ak = (tid & 3) << 2;
            float4 va = *(const float4*)(A + (size_t)(bm + ar) * K + k0 + ak);
            As[ak + 0][ar] = va.x;
            As[ak + 1][ar] = va.y;
            As[ak + 2][ar] = va.z;
            As[ak + 3][ar] = va.w;
        }
        // Load B tile (16x128): 2 float4 per thread, coalesced
        #pragma unroll
        for (int it = 0; it < 2; ++it) {
            const int br = (tid >> 5) + it * 8;
            const int bc = (tid & 31) << 2;
            *(float4*)&Bs[br][bc] =
                *(const float4*)(B + (size_t)(k0 + br) * N + bn + bc);
        }
        __syncthreads();

        #pragma unroll
        for (int kk = 0; kk < BK; ++kk) {
            float4 a0 = *(const float4*)&As[kk][4 * ty];
            float4 a1 = *(const float4*)&As[kk][64 + 4 * ty];
            float4 b0 = *(const float4*)&Bs[kk][4 * tx];
            float4 b1 = *(const float4*)&Bs[kk][64 + 4 * tx];
            const float ar0[4] = {a0.x, a0.y, a0.z, a0.w};
            const float ar1[4] = {a1.x, a1.y, a1.z, a1.w};
            const float br0[4] = {b0.x, b0.y, b0.z, b0.w};
            const float br1[4] = {b1.x, b1.y, b1.z, b1.w};
            #pragma unroll
            for (int e = 0; e < 4; ++e) {
                #pragma unroll
                for (int f = 0; f < 4; ++f) {
                    acc[0][0][e][f] += ar0[e] * br0[f];
                    acc[0][1][e][f] += ar0[e] * br1[f];
                    acc[1][0][e][f] += ar1[e] * br0[f];
                    acc[1][1][e][f] += ar1[e] * br1[f];
                }
            }
        }
        __syncthreads();
    }

    // Epilogue: optional residual add, float4 stores
    #pragma unroll
    for (int rh = 0; rh < 2; ++rh) {
        #pragma unroll
        for (int e = 0; e < 4; ++e) {
            const int row = bm + rh * 64 + 4 * ty + e;
            #pragma unroll
            for (int ch = 0; ch < 2; ++ch) {
                const int col = bn + ch * 64 + 4 * tx;
                float4 o;
                o.x = acc[rh][ch][e][0];
                o.y = acc[rh][ch][e][1];
                o.z = acc[rh][ch][e][2];
                o.w = acc[rh][ch][e][3];
                if (R) {
                    float4 rv = *(const float4*)(R + (size_t)row * N + col);
                    o.x += rv.x; o.y += rv.y; o.z += rv.z; o.w += rv.w;
                }
                *(float4*)(C + (size_t)row * N + col) = o;
            }
        }
    }
}

// ---------------------------------------------------------------------------
// Flash attention (fp32): one block per (q-tile of 64 rows, head).
// Online softmax, KV tiles of 64. 256 threads, each owns a 4x4 micro-tile.
// Shared (dynamic): Qt[d][r], Kt[d][c], Vs[c][d], Pt[c][r], each 64x65.
// ---------------------------------------------------------------------------
#define ATT_SMEM (4 * 64 * 65 * (int)sizeof(float))

__global__ void __launch_bounds__(256) attn_kernel(
    const float* __restrict__ Qg, const float* __restrict__ Kg,
    const float* __restrict__ Vg, float* __restrict__ Og)
{
    extern __shared__ float sm[];
    float* Qt = sm;                // [64][65]  d-major
    float* Kt = sm + 64 * 65;      // [64][65]  d-major
    float* Vs = sm + 2 * 64 * 65;  // [64][65]  c-major (row = kv index)
    float* Pt = sm + 3 * 64 * 65;  // [64][65]  j-major (Pt[j][i])

    const int tid  = threadIdx.x;
    const int ty   = tid >> 4;     // 0..15 -> q rows 4*ty..4*ty+3
    const int tx   = tid & 15;     // 0..15 -> kv cols / d cols 4*tx..
    const int i0   = blockIdx.x * 64;
    const int hoff = blockIdx.y * HD;

    // Load Q tile transposed, scale folded (HD^-0.5 = 1/8)
    {
        const float scale = 0.125f;
        #pragma unroll
        for (int it = 0; it < 4; ++it) {
            const int r  = it * 16 + (tid >> 4);
            const int c4 = (tid & 15) << 2;
            float4 v4 = *(const float4*)(Qg + (size_t)(i0 + r) * HDIM + hoff + c4);
            Qt[(c4 + 0) * 65 + r] = v4.x * scale;
            Qt[(c4 + 1) * 65 + r] = v4.y * scale;
            Qt[(c4 + 2) * 65 + r] = v4.z * scale;
            Qt[(c4 + 3) * 65 + r] = v4.w * scale;
        }
    }

    float m[4] = {-1e30f, -1e30f, -1e30f, -1e30f};
    float l[4] = {0.f, 0.f, 0.f, 0.f};
    float acc[4][4] = {};

    for (int j0 = 0; j0 < SQ; j0 += 64) {
        __syncthreads();  // prev-iter consumers done; also fences Q load on iter 0
        // Load K (transposed) and V (natural) tiles
        #pragma unroll
        for (int it = 0; it < 4; ++it) {
            const int r  = it * 16 + (tid >> 4);
            const int c4 = (tid & 15) << 2;
            float4 kv = *(const float4*)(Kg + (size_t)(j0 + r) * HDIM + hoff + c4);
            Kt[(c4 + 0) * 65 + r] = kv.x;
            Kt[(c4 + 1) * 65 + r] = kv.y;
            Kt[(c4 + 2) * 65 + r] = kv.z;
            Kt[(c4 + 3) * 65 + r] = kv.w;
            float4 vv = *(const float4*)(Vg + (size_t)(j0 + r) * HDIM + hoff + c4);
            Vs[r * 65 + c4 + 0] = vv.x;
            Vs[r * 65 + c4 + 1] = vv.y;
            Vs[r * 65 + c4 + 2] = vv.z;
            Vs[r * 65 + c4 + 3] = vv.w;
        }
        __syncthreads();

        // S = Q K^T (scaled)
        float s[4][4] = {};
        #pragma unroll 8
        for (int d = 0; d < HD; ++d) {
            float qa[4], kb[4];
            #pragma unroll
            for (int e = 0; e < 4; ++e) qa[e] = Qt[d * 65 + 4 * ty + e];
            #pragma unroll
            for (int f = 0; f < 4; ++f) kb[f] = Kt[d * 65 + 4 * tx + f];
            #pragma unroll
            for (int e = 0; e < 4; ++e)
                #pragma unroll
                for (int f = 0; f < 4; ++f)
                    s[e][f] += qa[e] * kb[f];
        }

        // Online softmax per row; write P transposed to shared
        #pragma unroll
        for (int e = 0; e < 4; ++e) {
            float mt = s[e][0];
            #pragma unroll
            for (int f = 1; f < 4; ++f) mt = fmaxf(mt, s[e][f]);
            #pragma unroll
            for (int o = 8; o; o >>= 1)
                mt = fmaxf(mt, __shfl_xor_sync(0xffffffffu, mt, o));
            const float mnew = fmaxf(m[e], mt);
            const float corr = __expf(m[e] - mnew);
            m[e] = mnew;
            float ps = 0.f;
            #pragma unroll
            for (int f = 0; f < 4; ++f) {
                const float p = __expf(s[e][f] - mnew);
                s[e][f] = p;
                ps += p;
            }
            #pragma unroll
            for (int o = 8; o; o >>= 1)
                ps += __shfl_xor_sync(0xffffffffu, ps, o);
            l[e] = l[e] * corr + ps;
            #pragma unroll
            for (int f = 0; f < 4; ++f) {
                acc[e][f] *= corr;
                Pt[(4 * tx + f) * 65 + 4 * ty + e] = s[e][f];
            }
        }
        __syncthreads();

        // O += P @ V
        #pragma unroll 8
        for (int j = 0; j < 64; ++j) {
            float pa[4], vb[4];
            #pragma unroll
            for (int e = 0; e < 4; ++e) pa[e] = Pt[j * 65 + 4 * ty + e];
            #pragma unroll
            for (int f = 0; f < 4; ++f) vb[f] = Vs[j * 65 + 4 * tx + f];
            #pragma unroll
            for (int e = 0; e < 4; ++e)
                #pragma unroll
                for (int f = 0; f < 4; ++f)
                    acc[e][f] += pa[e] * vb[f];
        }
    }

    // Normalize and write out
    #pragma unroll
    for (int e = 0; e < 4; ++e) {
        const float inv = 1.0f / l[e];
        float4 o4 = make_float4(acc[e][0] * inv, acc[e][1] * inv,
                                acc[e][2] * inv, acc[e][3] * inv);
        *(float4*)(Og + (size_t)(i0 + 4 * ty + e) * HDIM + hoff + 4 * tx) = o4;
    }
}

// ---------------------------------------------------------------------------
// SwiGLU elementwise: gu = silu(g) * u (vectorized float4)
// ---------------------------------------------------------------------------
__global__ void __launch_bounds__(256) silu_mul_kernel(
    const float* __restrict__ g, const float* __restrict__ u,
    float* __restrict__ out, int n4)
{
    const int i = blockIdx.x * blockDim.x + threadIdx.x;
    if (i >= n4) return;
    float4 gv = ((const float4*)g)[i];
    float4 uv = ((const float4*)u)[i];
    float4 o;
    o.x = gv.x * (1.0f / (1.0f + __expf(-gv.x))) * uv.x;
    o.y = gv.y * (1.0f / (1.0f + __expf(-gv.y))) * uv.y;
    o.z = gv.z * (1.0f / (1.0f + __expf(-gv.z))) * uv.z;
    o.w = gv.w * (1.0f / (1.0f + __expf(-gv.w))) * uv.w;
    ((float4*)out)[i] = o;
}

// ---------------------------------------------------------------------------
// Launch sequence
// ---------------------------------------------------------------------------
extern "C" void kernel_launch(void* const* d_in, const int* in_sizes, int n_in,
                              void* d_out, int out_size)
{
    (void)in_sizes; (void)n_in; (void)out_size;

    const float* hidden   = (const float*)d_in[0];
    const float* context  = (const float*)d_in[1];
    const float* sa_norm  = (const float*)d_in[2];
    const float* sa_wq    = (const float*)d_in[3];
    const float* sa_wk    = (const float*)d_in[4];
    const float* sa_wv    = (const float*)d_in[5];
    const float* sa_wo    = (const float*)d_in[6];
    const float* ca_norm  = (const float*)d_in[7];
    const float* ca_wq    = (const float*)d_in[8];
    const float* ca_wk    = (const float*)d_in[9];
    const float* ca_wv    = (const float*)d_in[10];
    const float* ca_wo    = (const float*)d_in[11];
    const float* mlp_norm = (const float*)d_in[12];
    const float* w_gate   = (const float*)d_in[13];
    const float* w_up     = (const float*)d_in[14];
    const float* w_down   = (const float*)d_in[15];
    float* out = (float*)d_out;

    float *xn, *q, *k, *v, *att, *h1, *h2, *gate, *up, *gu;
    cudaGetSymbolAddress((void**)&xn,   g_xn);
    cudaGetSymbolAddress((void**)&q,    g_q);
    cudaGetSymbolAddress((void**)&k,    g_k);
    cudaGetSymbolAddress((void**)&v,    g_v);
    cudaGetSymbolAddress((void**)&att,  g_att);
    cudaGetSymbolAddress((void**)&h1,   g_h1);
    cudaGetSymbolAddress((void**)&h2,   g_h2);
    cudaGetSymbolAddress((void**)&gate, g_gate);
    cudaGetSymbolAddress((void**)&up,   g_up);
    cudaGetSymbolAddress((void**)&gu,   g_gu);

    cudaFuncSetAttribute(attn_kernel,
                         cudaFuncAttributeMaxDynamicSharedMemorySize, ATT_SMEM);

    const dim3 blk(256);
    const dim3 g1024(HDIM / BN, SQ / BM);   // (8, 16)
    const dim3 g4096(ISZ / BN, SQ / BM);    // (32, 16)
    const dim3 gatt(SQ / 64, NH);           // (32, 16)

    // ---- Self-attention block ----
    rmsnorm_kernel<<<SQ, blk>>>(hidden, sa_norm, xn);
    sgemm_kernel<<<g1024, blk>>>(xn, sa_wq, nullptr, q, SQ, HDIM, HDIM);
    sgemm_kernel<<<g1024, blk>>>(xn, sa_wk, nullptr, k, SQ, HDIM, HDIM);
    sgemm_kernel<<<g1024, blk>>>(xn, sa_wv, nullptr, v, SQ, HDIM, HDIM);
    attn_kernel<<<gatt, blk, ATT_SMEM>>>(q, k, v, att);
    sgemm_kernel<<<g1024, blk>>>(att, sa_wo, hidden, h1, SQ, HDIM, HDIM);

    // ---- Cross-attention block (K/V from raw context) ----
    rmsnorm_kernel<<<SQ, blk>>>(h1, ca_norm, xn);
    sgemm_kernel<<<g1024, blk>>>(xn, ca_wq, nullptr, q, SQ, HDIM, HDIM);
    sgemm_kernel<<<g1024, blk>>>(context, ca_wk, nullptr, k, SQ, HDIM, HDIM);
    sgemm_kernel<<<g1024, blk>>>(context, ca_wv, nullptr, v, SQ, HDIM, HDIM);
    attn_kernel<<<gatt, blk, ATT_SMEM>>>(q, k, v, att);
    sgemm_kernel<<<g1024, blk>>>(att, ca_wo, h1, h2, SQ, HDIM, HDIM);

    // ---- MLP block ----
    rmsnorm_kernel<<<SQ, blk>>>(h2, mlp_norm, xn);
    sgemm_kernel<<<g4096, blk>>>(xn, w_gate, nullptr, gate, SQ, ISZ, HDIM);
    sgemm_kernel<<<g4096, blk>>>(xn, w_up, nullptr, up, SQ, ISZ, HDIM);
    silu_mul_kernel<<<(SQ * ISZ / 4 + 255) / 256, blk>>>(gate, up, gu, SQ * ISZ / 4);
    sgemm_kernel<<<g1024, blk>>>(gu, w_down, h2, out, SQ, HDIM, ISZ);
}

// round 2
// speedup vs baseline: 2.0548x; 2.0548x over previous
#include <cuda_runtime.h>
#include <math.h>
#include <stdint.h>

// ---------------------------------------------------------------------------
// Problem dimensions (fixed by the reference)
// ---------------------------------------------------------------------------
#define SQ   2048
#define HDIM 1024
#define NH   16
#define HD   64
#define ISZ  4096

// ---------------------------------------------------------------------------
// Scratch
// ---------------------------------------------------------------------------
__device__ float g_xn [SQ * HDIM];
__device__ float g_q  [SQ * HDIM];
__device__ float g_k  [SQ * HDIM];
__device__ float g_v  [SQ * HDIM];
__device__ float g_att[SQ * HDIM];
__device__ float g_h1 [SQ * HDIM];
__device__ float g_h2 [SQ * HDIM];
__device__ float g_gate[SQ * ISZ];
__device__ float g_up  [SQ * ISZ];
__device__ float g_gu  [SQ * ISZ];

// ---------------------------------------------------------------------------
// tf32 helpers
// ---------------------------------------------------------------------------
__device__ __forceinline__ uint32_t f2tf(float f) {
    uint32_t r;
    asm("cvt.rna.tf32.f32 %0, %1;" : "=r"(r) : "f"(f));
    return r;
}

__device__ __forceinline__ void mma_tf32(float* c, const uint32_t* a,
                                         uint32_t b0, uint32_t b1) {
    asm volatile(
        "mma.sync.aligned.m16n8k8.row.col.f32.tf32.tf32.f32 "
        "{%0,%1,%2,%3}, {%4,%5,%6,%7}, {%8,%9}, {%0,%1,%2,%3};"
        : "+f"(c[0]), "+f"(c[1]), "+f"(c[2]), "+f"(c[3])
        : "r"(a[0]), "r"(a[1]), "r"(a[2]), "r"(a[3]), "r"(b0), "r"(b1));
}

// ---------------------------------------------------------------------------
// RMSNorm (unchanged fp32)
// ---------------------------------------------------------------------------
__global__ void __launch_bounds__(256) rmsnorm_kernel(
    const float* __restrict__ x, const float* __restrict__ w,
    float* __restrict__ y)
{
    const int row = blockIdx.x;
    const int t   = threadIdx.x;
    float4 vx = ((const float4*)(x + (size_t)row * HDIM))[t];
    float s = vx.x*vx.x + vx.y*vx.y + vx.z*vx.z + vx.w*vx.w;
    #pragma unroll
    for (int o = 16; o; o >>= 1) s += __shfl_xor_sync(0xffffffffu, s, o);

    __shared__ float red[8];
    __shared__ float s_inv;
    if ((t & 31) == 0) red[t >> 5] = s;
    __syncthreads();
    if (t == 0) {
        float tot = 0.f;
        #pragma unroll
        for (int i = 0; i < 8; ++i) tot += red[i];
        s_inv = 1.0f / sqrtf(tot * (1.0f / (float)HDIM) + 1e-6f);
    }
    __syncthreads();
    const float r = s_inv;
    float4 vw = ((const float4*)w)[t];
    float4 o4 = make_float4(vx.x*r*vw.x, vx.y*r*vw.y, vx.z*r*vw.z, vx.w*r*vw.w);
    ((float4*)(y + (size_t)row * HDIM))[t] = o4;
}

// ---------------------------------------------------------------------------
// tf32 tensor-core GEMM: C[M,N] = A[M,K] @ B[K,N] (+R), row-major.
// 128x128x16 block tile, 8 warps (4m x 2n), warp tile 32x64 (2x8 mma tiles).
// ---------------------------------------------------------------------------
#define GA_LD 20    // As stride (words); 20 mod 32 -> conflict-free frag loads
#define GB_LD 132   // Bs stride

__global__ void __launch_bounds__(256) gemm_tf32_kernel(
    const float* __restrict__ A, const float* __restrict__ B,
    const float* __restrict__ R, float* __restrict__ C,
    int M, int N, int K)
{
    __shared__ uint32_t As[128 * GA_LD];
    __shared__ uint32_t Bs[16 * GB_LD];

    const int tid  = threadIdx.x;
    const int lane = tid & 31;
    const int wid  = tid >> 5;
    const int g    = lane >> 2;   // groupID
    const int tig  = lane & 3;    // thread-in-group
    const int wm   = (wid >> 1) * 32;
    const int wn   = (wid & 1) * 64;
    const int bm   = blockIdx.y * 128;
    const int bn   = blockIdx.x * 128;

    float acc[2][8][4];
    #pragma unroll
    for (int mt = 0; mt < 2; ++mt)
        #pragma unroll
        for (int nt = 0; nt < 8; ++nt)
            #pragma unroll
            for (int e = 0; e < 4; ++e) acc[mt][nt][e] = 0.f;

    for (int k0 = 0; k0 < K; k0 += 16) {
        // A tile 128x16 -> As[row][k] (tf32-converted)
        #pragma unroll
        for (int it = 0; it < 2; ++it) {
            const int r  = it * 64 + (tid >> 2);
            const int kc = (tid & 3) << 2;
            float4 v = *(const float4*)(A + (size_t)(bm + r) * K + k0 + kc);
            As[r * GA_LD + kc + 0] = f2tf(v.x);
            As[r * GA_LD + kc + 1] = f2tf(v.y);
            As[r * GA_LD + kc + 2] = f2tf(v.z);
            As[r * GA_LD + kc + 3] = f2tf(v.w);
        }
        // B tile 16x128 -> Bs[k][n]
        #pragma unroll
        for (int it = 0; it < 2; ++it) {
            const int r  = it * 8 + (tid >> 5);
            const int cc = (tid & 31) << 2;
            float4 v = *(const float4*)(B + (size_t)(k0 + r) * N + bn + cc);
            Bs[r * GB_LD + cc + 0] = f2tf(v.x);
            Bs[r * GB_LD + cc + 1] = f2tf(v.y);
            Bs[r * GB_LD + cc + 2] = f2tf(v.z);
            Bs[r * GB_LD + cc + 3] = f2tf(v.w);
        }
        __syncthreads();

        #pragma unroll
        for (int kt = 0; kt < 2; ++kt) {
            uint32_t bf[8][2];
            #pragma unroll
            for (int nt = 0; nt < 8; ++nt) {
                const int n = wn + nt * 8 + g;
                bf[nt][0] = Bs[(kt * 8 + tig)     * GB_LD + n];
                bf[nt][1] = Bs[(kt * 8 + tig + 4) * GB_LD + n];
            }
            #pragma unroll
            for (int mt = 0; mt < 2; ++mt) {
                uint32_t a[4];
                const int base = (wm + mt * 16 + g) * GA_LD + kt * 8 + tig;
                a[0] = As[base];
                a[1] = As[base + 8 * GA_LD];
                a[2] = As[base + 4];
                a[3] = As[base + 8 * GA_LD + 4];
                #pragma unroll
                for (int nt = 0; nt < 8; ++nt)
                    mma_tf32(acc[mt][nt], a, bf[nt][0], bf[nt][1]);
            }
        }
        __syncthreads();
    }

    // Epilogue: C fragment rows g, g+8; cols 2*tig, 2*tig+1
    #pragma unroll
    for (int mt = 0; mt < 2; ++mt) {
        const int r0 = bm + wm + mt * 16 + g;
        const int r1 = r0 + 8;
        #pragma unroll
        for (int nt = 0; nt < 8; ++nt) {
            const int col = bn + wn + nt * 8 + 2 * tig;
            float2 v0 = make_float2(acc[mt][nt][0], acc[mt][nt][1]);
            float2 v1 = make_float2(acc[mt][nt][2], acc[mt][nt][3]);
            if (R) {
                float2 a0 = *(const float2*)(R + (size_t)r0 * N + col);
                float2 a1 = *(const float2*)(R + (size_t)r1 * N + col);
                v0.x += a0.x; v0.y += a0.y;
                v1.x += a1.x; v1.y += a1.y;
            }
            *(float2*)(C + (size_t)r0 * N + col) = v0;
            *(float2*)(C + (size_t)r1 * N + col) = v1;
        }
    }
}

// ---------------------------------------------------------------------------
// Flash attention with tf32 mma. Block = 128 q-rows x 1 head, 8 warps.
// Each warp owns 16 q-rows x full 64 kv-cols -> softmax rows stay in-warp.
// ---------------------------------------------------------------------------
#define AQ_LD 68   // Qs/Ks stride: 68 mod 32 = 4 -> conflict-free frag loads
#define AV_LD 67   // Vt stride: ~2-way on both store and load (compromise)
#define ATT_SMEM ((128 * AQ_LD + 64 * AQ_LD + 64 * AV_LD) * 4)

__global__ void __launch_bounds__(256) attn_tc_kernel(
    const float* __restrict__ Qg, const float* __restrict__ Kg,
    const float* __restrict__ Vg, float* __restrict__ Og)
{
    extern __shared__ uint32_t sm[];
    uint32_t* Qs = sm;                               // [128][AQ_LD]
    uint32_t* Ks = sm + 128 * AQ_LD;                 // [64][AQ_LD]
    uint32_t* Vt = sm + 128 * AQ_LD + 64 * AQ_LD;    // [64][AV_LD] (d-major)

    const int tid  = threadIdx.x;
    const int lane = tid & 31;
    const int wid  = tid >> 5;
    const int g    = lane >> 2;
    const int tig  = lane & 3;
    const int i0   = blockIdx.x * 128;
    const int hoff = blockIdx.y * HD;
    const int qrow = wid * 16;

    // Load Q tile (scale folded), tf32-converted
    {
        const float scale = 0.125f;
        #pragma unroll
        for (int it = 0; it < 8; ++it) {
            const int r  = it * 16 + (tid >> 4);
            const int c4 = (tid & 15) << 2;
            float4 v = *(const float4*)(Qg + (size_t)(i0 + r) * HDIM + hoff + c4);
            Qs[r * AQ_LD + c4 + 0] = f2tf(v.x * scale);
            Qs[r * AQ_LD + c4 + 1] = f2tf(v.y * scale);
            Qs[r * AQ_LD + c4 + 2] = f2tf(v.z * scale);
            Qs[r * AQ_LD + c4 + 3] = f2tf(v.w * scale);
        }
    }

    float m0 = -1e30f, m1 = -1e30f;
    float l0 = 0.f, l1 = 0.f;
    float o[8][4];
    #pragma unroll
    for (int nt = 0; nt < 8; ++nt)
        #pragma unroll
        for (int e = 0; e < 4; ++e) o[nt][e] = 0.f;

    for (int j0 = 0; j0 < SQ; j0 += 64) {
        __syncthreads();
        // Load K natural [j][d], V transposed [d][j]
        #pragma unroll
        for (int it = 0; it < 4; ++it) {
            const int r  = it * 16 + (tid >> 4);
            const int c4 = (tid & 15) << 2;
            float4 kv = *(const float4*)(Kg + (size_t)(j0 + r) * HDIM + hoff + c4);
            Ks[r * AQ_LD + c4 + 0] = f2tf(kv.x);
            Ks[r * AQ_LD + c4 + 1] = f2tf(kv.y);
            Ks[r * AQ_LD + c4 + 2] = f2tf(kv.z);
            Ks[r * AQ_LD + c4 + 3] = f2tf(kv.w);
            float4 vv = *(const float4*)(Vg + (size_t)(j0 + r) * HDIM + hoff + c4);
            Vt[(c4 + 0) * AV_LD + r] = f2tf(vv.x);
            Vt[(c4 + 1) * AV_LD + r] = f2tf(vv.y);
            Vt[(c4 + 2) * AV_LD + r] = f2tf(vv.z);
            Vt[(c4 + 3) * AV_LD + r] = f2tf(vv.w);
        }
        __syncthreads();

        // S = Q K^T : warp computes 16 x 64
        float s[8][4];
        #pragma unroll
        for (int nt = 0; nt < 8; ++nt)
            #pragma unroll
            for (int e = 0; e < 4; ++e) s[nt][e] = 0.f;

        #pragma unroll
        for (int kt = 0; kt < 8; ++kt) {
            uint32_t a[4];
            const int base = (qrow + g) * AQ_LD + kt * 8 + tig;
            a[0] = Qs[base];
            a[1] = Qs[base + 8 * AQ_LD];
            a[2] = Qs[base + 4];
            a[3] = Qs[base + 8 * AQ_LD + 4];
            #pragma unroll
            for (int nt = 0; nt < 8; ++nt) {
                const int jb = (nt * 8 + g) * AQ_LD + kt * 8 + tig;
                mma_tf32(s[nt], a, Ks[jb], Ks[jb + 4]);
            }
        }

        // Online softmax. Thread rows: g (regs 0,1), g+8 (regs 2,3).
        float mt0 = -1e30f, mt1 = -1e30f;
        #pragma unroll
        for (int nt = 0; nt < 8; ++nt) {
            mt0 = fmaxf(mt0, fmaxf(s[nt][0], s[nt][1]));
            mt1 = fmaxf(mt1, fmaxf(s[nt][2], s[nt][3]));
        }
        mt0 = fmaxf(mt0, __shfl_xor_sync(0xffffffffu, mt0, 1));
        mt0 = fmaxf(mt0, __shfl_xor_sync(0xffffffffu, mt0, 2));
        mt1 = fmaxf(mt1, __shfl_xor_sync(0xffffffffu, mt1, 1));
        mt1 = fmaxf(mt1, __shfl_xor_sync(0xffffffffu, mt1, 2));

        const float mn0 = fmaxf(m0, mt0);
        const float mn1 = fmaxf(m1, mt1);
        const float c0 = __expf(m0 - mn0);
        const float c1 = __expf(m1 - mn1);
        m0 = mn0; m1 = mn1;

        float ps0 = 0.f, ps1 = 0.f;
        #pragma unroll
        for (int nt = 0; nt < 8; ++nt) {
            s[nt][0] = __expf(s[nt][0] - mn0);
            s[nt][1] = __expf(s[nt][1] - mn0);
            s[nt][2] = __expf(s[nt][2] - mn1);
            s[nt][3] = __expf(s[nt][3] - mn1);
            ps0 += s[nt][0] + s[nt][1];
            ps1 += s[nt][2] + s[nt][3];
        }
        ps0 += __shfl_xor_sync(0xffffffffu, ps0, 1);
        ps0 += __shfl_xor_sync(0xffffffffu, ps0, 2);
        ps1 += __shfl_xor_sync(0xffffffffu, ps1, 1);
        ps1 += __shfl_xor_sync(0xffffffffu, ps1, 2);
        l0 = l0 * c0 + ps0;
        l1 = l1 * c1 + ps1;

        #pragma unroll
        for (int nt = 0; nt < 8; ++nt) {
            o[nt][0] *= c0; o[nt][1] *= c0;
            o[nt][2] *= c1; o[nt][3] *= c1;
        }

        // O += P @ V. Build A-fragments of P from C-fragment regs via shfl.
        const int l1i = (lane & ~3) | (tig >> 1);
        const int l2i = (lane & ~3) | ((tig >> 1) + 2);
        const bool odd = (tig & 1);
        #pragma unroll
        for (int jt = 0; jt < 8; ++jt) {
            float e0 = __shfl_sync(0xffffffffu, s[jt][0], l1i);
            float q0 = __shfl_sync(0xffffffffu, s[jt][1], l1i);
            float e1 = __shfl_sync(0xffffffffu, s[jt][2], l1i);
            float q1 = __shfl_sync(0xffffffffu, s[jt][3], l1i);
            float e2 = __shfl_sync(0xffffffffu, s[jt][0], l2i);
            float q2 = __shfl_sync(0xffffffffu, s[jt][1], l2i);
            float e3 = __shfl_sync(0xffffffffu, s[jt][2], l2i);
            float q3 = __shfl_sync(0xffffffffu, s[jt][3], l2i);
            uint32_t a[4];
            a[0] = f2tf(odd ? q0 : e0);
            a[1] = f2tf(odd ? q1 : e1);
            a[2] = f2tf(odd ? q2 : e2);
            a[3] = f2tf(odd ? q3 : e3);
            #pragma unroll
            for (int nt = 0; nt < 8; ++nt) {
                const int vb = (nt * 8 + g) * AV_LD + jt * 8 + tig;
                mma_tf32(o[nt], a, Vt[vb], Vt[vb + 4]);
            }
        }
    }

    // Normalize + store
    const float i0f = 1.0f / l0;
    const float i1f = 1.0f / l1;
    const int r0 = i0 + qrow + g;
    const int r1 = r0 + 8;
    #pragma unroll
    for (int nt = 0; nt < 8; ++nt) {
        const int col = hoff + nt * 8 + 2 * tig;
        *(float2*)(Og + (size_t)r0 * HDIM + col) =
            make_float2(o[nt][0] * i0f, o[nt][1] * i0f);
        *(float2*)(Og + (size_t)r1 * HDIM + col) =
            make_float2(o[nt][2] * i1f, o[nt][3] * i1f);
    }
}

// ---------------------------------------------------------------------------
// SwiGLU elementwise
// ---------------------------------------------------------------------------
__global__ void __launch_bounds__(256) silu_mul_kernel(
    const float* __restrict__ g, const float* __restrict__ u,
    float* __restrict__ out, int n4)
{
    const int i = blockIdx.x * blockDim.x + threadIdx.x;
    if (i >= n4) return;
    float4 gv = ((const float4*)g)[i];
    float4 uv = ((const float4*)u)[i];
    float4 o;
    o.x = gv.x * (1.0f / (1.0f + __expf(-gv.x))) * uv.x;
    o.y = gv.y * (1.0f / (1.0f + __expf(-gv.y))) * uv.y;
    o.z = gv.z * (1.0f / (1.0f + __expf(-gv.z))) * uv.z;
    o.w = gv.w * (1.0f / (1.0f + __expf(-gv.w))) * uv.w;
    ((float4*)out)[i] = o;
}

// ---------------------------------------------------------------------------
// Launch sequence
// ---------------------------------------------------------------------------
extern "C" void kernel_launch(void* const* d_in, const int* in_sizes, int n_in,
                              void* d_out, int out_size)
{
    (void)in_sizes; (void)n_in; (void)out_size;

    const float* hidden   = (const float*)d_in[0];
    const float* context  = (const float*)d_in[1];
    const float* sa_norm  = (const float*)d_in[2];
    const float* sa_wq    = (const float*)d_in[3];
    const float* sa_wk    = (const float*)d_in[4];
    const float* sa_wv    = (const float*)d_in[5];
    const float* sa_wo    = (const float*)d_in[6];
    const float* ca_norm  = (const float*)d_in[7];
    const float* ca_wq    = (const float*)d_in[8];
    const float* ca_wk    = (const float*)d_in[9];
    const float* ca_wv    = (const float*)d_in[10];
    const float* ca_wo    = (const float*)d_in[11];
    const float* mlp_norm = (const float*)d_in[12];
    const float* w_gate   = (const float*)d_in[13];
    const float* w_up     = (const float*)d_in[14];
    const float* w_down   = (const float*)d_in[15];
    float* out = (float*)d_out;

    float *xn, *q, *k, *v, *att, *h1, *h2, *gate, *up, *gu;
    cudaGetSymbolAddress((void**)&xn,   g_xn);
    cudaGetSymbolAddress((void**)&q,    g_q);
    cudaGetSymbolAddress((void**)&k,    g_k);
    cudaGetSymbolAddress((void**)&v,    g_v);
    cudaGetSymbolAddress((void**)&att,  g_att);
    cudaGetSymbolAddress((void**)&h1,   g_h1);
    cudaGetSymbolAddress((void**)&h2,   g_h2);
    cudaGetSymbolAddress((void**)&gate, g_gate);
    cudaGetSymbolAddress((void**)&up,   g_up);
    cudaGetSymbolAddress((void**)&gu,   g_gu);

    cudaFuncSetAttribute(attn_tc_kernel,
                         cudaFuncAttributeMaxDynamicSharedMemorySize, ATT_SMEM);

    const dim3 blk(256);
    const dim3 g1024(HDIM / 128, SQ / 128);   // (8, 16)
    const dim3 g4096(ISZ / 128, SQ / 128);    // (32, 16)
    const dim3 gatt(SQ / 128, NH);            // (16, 16)

    // ---- Self-attention block ----
    rmsnorm_kernel<<<SQ, blk>>>(hidden, sa_norm, xn);
    gemm_tf32_kernel<<<g1024, blk>>>(xn, sa_wq, nullptr, q, SQ, HDIM, HDIM);
    gemm_tf32_kernel<<<g1024, blk>>>(xn, sa_wk, nullptr, k, SQ, HDIM, HDIM);
    gemm_tf32_kernel<<<g1024, blk>>>(xn, sa_wv, nullptr, v, SQ, HDIM, HDIM);
    attn_tc_kernel<<<gatt, blk, ATT_SMEM>>>(q, k, v, att);
    gemm_tf32_kernel<<<g1024, blk>>>(att, sa_wo, hidden, h1, SQ, HDIM, HDIM);

    // ---- Cross-attention block ----
    rmsnorm_kernel<<<SQ, blk>>>(h1, ca_norm, xn);
    gemm_tf32_kernel<<<g1024, blk>>>(xn, ca_wq, nullptr, q, SQ, HDIM, HDIM);
    gemm_tf32_kernel<<<g1024, blk>>>(context, ca_wk, nullptr, k, SQ, HDIM, HDIM);
    gemm_tf32_kernel<<<g1024, blk>>>(context, ca_wv, nullptr, v, SQ, HDIM, HDIM);
    attn_tc_kernel<<<gatt, blk, ATT_SMEM>>>(q, k, v, att);
    gemm_tf32_kernel<<<g1024, blk>>>(att, ca_wo, h1, h2, SQ, HDIM, HDIM);

    // ---- MLP block ----
    rmsnorm_kernel<<<SQ, blk>>>(h2, mlp_norm, xn);
    gemm_tf32_kernel<<<g4096, blk>>>(xn, w_gate, nullptr, gate, SQ, ISZ, HDIM);
    gemm_tf32_kernel<<<g4096, blk>>>(xn, w_up, nullptr, up, SQ, ISZ, HDIM);
    silu_mul_kernel<<<(SQ * ISZ / 4 + 255) / 256, blk>>>(gate, up, gu, SQ * ISZ / 4);
    gemm_tf32_kernel<<<g1024, blk>>>(gu, w_down, h2, out, SQ, HDIM, ISZ);
}

// round 3
// speedup vs baseline: 3.2325x; 1.5732x over previous
#include <cuda_runtime.h>
#include <math.h>
#include <stdint.h>

// ---------------------------------------------------------------------------
// Problem dimensions
// ---------------------------------------------------------------------------
#define SQ   2048
#define HDIM 1024
#define NH   16
#define HD   64
#define ISZ  4096

// ---------------------------------------------------------------------------
// Scratch
// ---------------------------------------------------------------------------
__device__ float g_xn [SQ * HDIM];
__device__ float g_q  [SQ * HDIM];
__device__ float g_k  [SQ * HDIM];
__device__ float g_v  [SQ * HDIM];
__device__ float g_att[SQ * HDIM];
__device__ float g_h1 [SQ * HDIM];
__device__ float g_h2 [SQ * HDIM];
__device__ float g_gate[SQ * ISZ];
__device__ float g_up  [SQ * ISZ];
__device__ float g_gu  [SQ * ISZ];

// ---------------------------------------------------------------------------
// Helpers
// ---------------------------------------------------------------------------
__device__ __forceinline__ uint32_t f2tf(float f) {
    uint32_t r;
    asm("cvt.rna.tf32.f32 %0, %1;" : "=r"(r) : "f"(f));
    return r;
}

__device__ __forceinline__ void mma_tf32(float* c, const uint32_t* a,
                                         uint32_t b0, uint32_t b1) {
    asm volatile(
        "mma.sync.aligned.m16n8k8.row.col.f32.tf32.tf32.f32 "
        "{%0,%1,%2,%3}, {%4,%5,%6,%7}, {%8,%9}, {%0,%1,%2,%3};"
        : "+f"(c[0]), "+f"(c[1]), "+f"(c[2]), "+f"(c[3])
        : "r"(a[0]), "r"(a[1]), "r"(a[2]), "r"(a[3]), "r"(b0), "r"(b1));
}

__device__ __forceinline__ void cp16(uint32_t smem_dst, const void* gsrc) {
    asm volatile("cp.async.ca.shared.global [%0], [%1], 16;\n"
                 :: "r"(smem_dst), "l"(gsrc));
}
__device__ __forceinline__ void cp_commit() {
    asm volatile("cp.async.commit_group;\n" ::: "memory");
}
template <int N>
__device__ __forceinline__ void cp_wait() {
    asm volatile("cp.async.wait_group %0;\n" :: "n"(N) : "memory");
}

// ---------------------------------------------------------------------------
// RMSNorm
// ---------------------------------------------------------------------------
__global__ void __launch_bounds__(256) rmsnorm_kernel(
    const float* __restrict__ x, const float* __restrict__ w,
    float* __restrict__ y)
{
    const int row = blockIdx.x;
    const int t   = threadIdx.x;
    float4 vx = ((const float4*)(x + (size_t)row * HDIM))[t];
    float s = vx.x*vx.x + vx.y*vx.y + vx.z*vx.z + vx.w*vx.w;
    #pragma unroll
    for (int o = 16; o; o >>= 1) s += __shfl_xor_sync(0xffffffffu, s, o);

    __shared__ float red[8];
    __shared__ float s_inv;
    if ((t & 31) == 0) red[t >> 5] = s;
    __syncthreads();
    if (t == 0) {
        float tot = 0.f;
        #pragma unroll
        for (int i = 0; i < 8; ++i) tot += red[i];
        s_inv = 1.0f / sqrtf(tot * (1.0f / (float)HDIM) + 1e-6f);
    }
    __syncthreads();
    const float r = s_inv;
    float4 vw = ((const float4*)w)[t];
    float4 o4 = make_float4(vx.x*r*vw.x, vx.y*r*vw.y, vx.z*r*vw.z, vx.w*r*vw.w);
    ((float4*)(y + (size_t)row * HDIM))[t] = o4;
}

// ---------------------------------------------------------------------------
// tf32 tensor-core GEMM with cp.async double buffering.
// C[M,N] = A[M,K] @ Bz[K,N] (+R), row-major. blockIdx.z selects (B,C) pair.
// 128x128x16 tile, 8 warps (4m x 2n), warp tile 32x64.
// Raw fp32 bits are fed to tf32 mma (HW truncation) — no cvt on load path.
// ---------------------------------------------------------------------------
#define GA_LD 20    // As row stride (words): conflict-free fragment loads
#define GB_LD 132   // Bs row stride (words)

__global__ void __launch_bounds__(256) gemm_tf32_kernel(
    const float* __restrict__ A,
    const float* __restrict__ B0, const float* __restrict__ B1,
    const float* __restrict__ B2,
    const float* __restrict__ R,
    float* __restrict__ C0, float* __restrict__ C1, float* __restrict__ C2,
    int M, int N, int K)
{
    __shared__ uint32_t As[2][128 * GA_LD];
    __shared__ uint32_t Bs[2][16 * GB_LD];

    const float* B = (blockIdx.z == 0) ? B0 : (blockIdx.z == 1 ? B1 : B2);
    float*       C = (blockIdx.z == 0) ? C0 : (blockIdx.z == 1 ? C1 : C2);

    const int tid  = threadIdx.x;
    const int lane = tid & 31;
    const int wid  = tid >> 5;
    const int g    = lane >> 2;
    const int tig  = lane & 3;
    const int wm   = (wid >> 1) * 32;
    const int wn   = (wid & 1) * 64;
    const int bm   = blockIdx.y * 128;
    const int bn   = blockIdx.x * 128;

    // Per-thread cp.async assignments (2 x 16B for A, 2 x 16B for B)
    const int a_r0 = tid >> 1;            // rows 0..127 (two chunks/row pattern)
    const int a_j0 = (tid & 1) << 3;      // float offset 0 or 8 (two 16B? no: 16 floats/row -> chunks at 0,4,8,12)
    // Use chunk id scheme instead: chunk = tid + it*256; r = chunk>>2; j = (chunk&3)*4
    const int b_rbase = tid >> 5;         // via chunk scheme below

    (void)a_r0; (void)a_j0; (void)b_rbase;

    float acc[2][8][4];
    #pragma unroll
    for (int mt = 0; mt < 2; ++mt)
        #pragma unroll
        for (int nt = 0; nt < 8; ++nt)
            #pragma unroll
            for (int e = 0; e < 4; ++e) acc[mt][nt][e] = 0.f;

    const int niter = K >> 4;

    // ---- tile load issue (stage s, k-tile index i) ----
    auto issue = [&](int i, int s) {
        const int k0 = i << 4;
        // A tile: 128x16 floats = 512 16B-chunks / 256 threads = 2 each
        #pragma unroll
        for (int it = 0; it < 2; ++it) {
            const int chunk = tid + it * 256;
            const int r = chunk >> 2;
            const int j = (chunk & 3) << 2;
            uint32_t dst = (uint32_t)__cvta_generic_to_shared(
                &As[s][r * GA_LD + j]);
            cp16(dst, A + (size_t)(bm + r) * K + k0 + j);
        }
        // B tile: 16x128 floats = 512 chunks
        #pragma unroll
        for (int it = 0; it < 2; ++it) {
            const int chunk = tid + it * 256;
            const int r = chunk >> 5;
            const int c = (chunk & 31) << 2;
            uint32_t dst = (uint32_t)__cvta_generic_to_shared(
                &Bs[s][r * GB_LD + c]);
            cp16(dst, B + (size_t)(k0 + r) * N + bn + c);
        }
    };

    issue(0, 0);
    cp_commit();

    for (int i = 0; i < niter; ++i) {
        const int s = i & 1;
        if (i + 1 < niter) issue(i + 1, s ^ 1);
        cp_commit();
        cp_wait<1>();          // tile i resident
        __syncthreads();

        #pragma unroll
        for (int kt = 0; kt < 2; ++kt) {
            uint32_t bf[8][2];
            #pragma unroll
            for (int nt = 0; nt < 8; ++nt) {
                const int n = wn + nt * 8 + g;
                bf[nt][0] = Bs[s][(kt * 8 + tig)     * GB_LD + n];
                bf[nt][1] = Bs[s][(kt * 8 + tig + 4) * GB_LD + n];
            }
            #pragma unroll
            for (int mt = 0; mt < 2; ++mt) {
                uint32_t a[4];
                const int base = (wm + mt * 16 + g) * GA_LD + kt * 8 + tig;
                a[0] = As[s][base];
                a[1] = As[s][base + 8 * GA_LD];
                a[2] = As[s][base + 4];
                a[3] = As[s][base + 8 * GA_LD + 4];
                #pragma unroll
                for (int nt = 0; nt < 8; ++nt)
                    mma_tf32(acc[mt][nt], a, bf[nt][0], bf[nt][1]);
            }
        }
        __syncthreads();       // protect stage s before its reuse at i+2
    }

    // Epilogue
    #pragma unroll
    for (int mt = 0; mt < 2; ++mt) {
        const int r0 = bm + wm + mt * 16 + g;
        const int r1 = r0 + 8;
        #pragma unroll
        for (int nt = 0; nt < 8; ++nt) {
            const int col = bn + wn + nt * 8 + 2 * tig;
            float2 v0 = make_float2(acc[mt][nt][0], acc[mt][nt][1]);
            float2 v1 = make_float2(acc[mt][nt][2], acc[mt][nt][3]);
            if (R) {
                float2 a0 = *(const float2*)(R + (size_t)r0 * N + col);
                float2 a1 = *(const float2*)(R + (size_t)r1 * N + col);
                v0.x += a0.x; v0.y += a0.y;
                v1.x += a1.x; v1.y += a1.y;
            }
            *(float2*)(C + (size_t)r0 * N + col) = v0;
            *(float2*)(C + (size_t)r1 * N + col) = v1;
        }
    }
}

// ---------------------------------------------------------------------------
// Flash attention with tf32 mma (as R2; proven correct)
// ---------------------------------------------------------------------------
#define AQ_LD 68
#define AV_LD 67
#define ATT_SMEM ((128 * AQ_LD + 64 * AQ_LD + 64 * AV_LD) * 4)

__global__ void __launch_bounds__(256) attn_tc_kernel(
    const float* __restrict__ Qg, const float* __restrict__ Kg,
    const float* __restrict__ Vg, float* __restrict__ Og)
{
    extern __shared__ uint32_t sm[];
    uint32_t* Qs = sm;
    uint32_t* Ks = sm + 128 * AQ_LD;
    uint32_t* Vt = sm + 128 * AQ_LD + 64 * AQ_LD;

    const int tid  = threadIdx.x;
    const int lane = tid & 31;
    const int wid  = tid >> 5;
    const int g    = lane >> 2;
    const int tig  = lane & 3;
    const int i0   = blockIdx.x * 128;
    const int hoff = blockIdx.y * HD;
    const int qrow = wid * 16;

    {
        const float scale = 0.125f;
        #pragma unroll
        for (int it = 0; it < 8; ++it) {
            const int r  = it * 16 + (tid >> 4);
            const int c4 = (tid & 15) << 2;
            float4 v = *(const float4*)(Qg + (size_t)(i0 + r) * HDIM + hoff + c4);
            Qs[r * AQ_LD + c4 + 0] = f2tf(v.x * scale);
            Qs[r * AQ_LD + c4 + 1] = f2tf(v.y * scale);
            Qs[r * AQ_LD + c4 + 2] = f2tf(v.z * scale);
            Qs[r * AQ_LD + c4 + 3] = f2tf(v.w * scale);
        }
    }

    float m0 = -1e30f, m1 = -1e30f;
    float l0 = 0.f, l1 = 0.f;
    float o[8][4];
    #pragma unroll
    for (int nt = 0; nt < 8; ++nt)
        #pragma unroll
        for (int e = 0; e < 4; ++e) o[nt][e] = 0.f;

    for (int j0 = 0; j0 < SQ; j0 += 64) {
        __syncthreads();
        #pragma unroll
        for (int it = 0; it < 4; ++it) {
            const int r  = it * 16 + (tid >> 4);
            const int c4 = (tid & 15) << 2;
            float4 kv = *(const float4*)(Kg + (size_t)(j0 + r) * HDIM + hoff + c4);
            Ks[r * AQ_LD + c4 + 0] = f2tf(kv.x);
            Ks[r * AQ_LD + c4 + 1] = f2tf(kv.y);
            Ks[r * AQ_LD + c4 + 2] = f2tf(kv.z);
            Ks[r * AQ_LD + c4 + 3] = f2tf(kv.w);
            float4 vv = *(const float4*)(Vg + (size_t)(j0 + r) * HDIM + hoff + c4);
            Vt[(c4 + 0) * AV_LD + r] = f2tf(vv.x);
            Vt[(c4 + 1) * AV_LD + r] = f2tf(vv.y);
            Vt[(c4 + 2) * AV_LD + r] = f2tf(vv.z);
            Vt[(c4 + 3) * AV_LD + r] = f2tf(vv.w);
        }
        __syncthreads();

        float s[8][4];
        #pragma unroll
        for (int nt = 0; nt < 8; ++nt)
            #pragma unroll
            for (int e = 0; e < 4; ++e) s[nt][e] = 0.f;

        #pragma unroll
        for (int kt = 0; kt < 8; ++kt) {
            uint32_t a[4];
            const int base = (qrow + g) * AQ_LD + kt * 8 + tig;
            a[0] = Qs[base];
            a[1] = Qs[base + 8 * AQ_LD];
            a[2] = Qs[base + 4];
            a[3] = Qs[base + 8 * AQ_LD + 4];
            #pragma unroll
            for (int nt = 0; nt < 8; ++nt) {
                const int jb = (nt * 8 + g) * AQ_LD + kt * 8 + tig;
                mma_tf32(s[nt], a, Ks[jb], Ks[jb + 4]);
            }
        }

        float mt0 = -1e30f, mt1 = -1e30f;
        #pragma unroll
        for (int nt = 0; nt < 8; ++nt) {
            mt0 = fmaxf(mt0, fmaxf(s[nt][0], s[nt][1]));
            mt1 = fmaxf(mt1, fmaxf(s[nt][2], s[nt][3]));
        }
        mt0 = fmaxf(mt0, __shfl_xor_sync(0xffffffffu, mt0, 1));
        mt0 = fmaxf(mt0, __shfl_xor_sync(0xffffffffu, mt0, 2));
        mt1 = fmaxf(mt1, __shfl_xor_sync(0xffffffffu, mt1, 1));
        mt1 = fmaxf(mt1, __shfl_xor_sync(0xffffffffu, mt1, 2));

        const float mn0 = fmaxf(m0, mt0);
        const float mn1 = fmaxf(m1, mt1);
        const float c0 = __expf(m0 - mn0);
        const float c1 = __expf(m1 - mn1);
        m0 = mn0; m1 = mn1;

        float ps0 = 0.f, ps1 = 0.f;
        #pragma unroll
        for (int nt = 0; nt < 8; ++nt) {
            s[nt][0] = __expf(s[nt][0] - mn0);
            s[nt][1] = __expf(s[nt][1] - mn0);
            s[nt][2] = __expf(s[nt][2] - mn1);
            s[nt][3] = __expf(s[nt][3] - mn1);
            ps0 += s[nt][0] + s[nt][1];
            ps1 += s[nt][2] + s[nt][3];
        }
        ps0 += __shfl_xor_sync(0xffffffffu, ps0, 1);
        ps0 += __shfl_xor_sync(0xffffffffu, ps0, 2);
        ps1 += __shfl_xor_sync(0xffffffffu, ps1, 1);
        ps1 += __shfl_xor_sync(0xffffffffu, ps1, 2);
        l0 = l0 * c0 + ps0;
        l1 = l1 * c1 + ps1;

        #pragma unroll
        for (int nt = 0; nt < 8; ++nt) {
            o[nt][0] *= c0; o[nt][1] *= c0;
            o[nt][2] *= c1; o[nt][3] *= c1;
        }

        const int l1i = (lane & ~3) | (tig >> 1);
        const int l2i = (lane & ~3) | ((tig >> 1) + 2);
        const bool odd = (tig & 1);
        #pragma unroll
        for (int jt = 0; jt < 8; ++jt) {
            float e0 = __shfl_sync(0xffffffffu, s[jt][0], l1i);
            float q0 = __shfl_sync(0xffffffffu, s[jt][1], l1i);
            float e1 = __shfl_sync(0xffffffffu, s[jt][2], l1i);
            float q1 = __shfl_sync(0xffffffffu, s[jt][3], l1i);
            float e2 = __shfl_sync(0xffffffffu, s[jt][0], l2i);
            float q2 = __shfl_sync(0xffffffffu, s[jt][1], l2i);
            float e3 = __shfl_sync(0xffffffffu, s[jt][2], l2i);
            float q3 = __shfl_sync(0xffffffffu, s[jt][3], l2i);
            uint32_t a[4];
            a[0] = f2tf(odd ? q0 : e0);
            a[1] = f2tf(odd ? q1 : e1);
            a[2] = f2tf(odd ? q2 : e2);
            a[3] = f2tf(odd ? q3 : e3);
            #pragma unroll
            for (int nt = 0; nt < 8; ++nt) {
                const int vb = (nt * 8 + g) * AV_LD + jt * 8 + tig;
                mma_tf32(o[nt], a, Vt[vb], Vt[vb + 4]);
            }
        }
    }

    const float i0f = 1.0f / l0;
    const float i1f = 1.0f / l1;
    const int r0 = i0 + qrow + g;
    const int r1 = r0 + 8;
    #pragma unroll
    for (int nt = 0; nt < 8; ++nt) {
        const int col = hoff + nt * 8 + 2 * tig;
        *(float2*)(Og + (size_t)r0 * HDIM + col) =
            make_float2(o[nt][0] * i0f, o[nt][1] * i0f);
        *(float2*)(Og + (size_t)r1 * HDIM + col) =
            make_float2(o[nt][2] * i1f, o[nt][3] * i1f);
    }
}

// ---------------------------------------------------------------------------
// SwiGLU elementwise
// ---------------------------------------------------------------------------
__global__ void __launch_bounds__(256) silu_mul_kernel(
    const float* __restrict__ g, const float* __restrict__ u,
    float* __restrict__ out, int n4)
{
    const int i = blockIdx.x * blockDim.x + threadIdx.x;
    if (i >= n4) return;
    float4 gv = ((const float4*)g)[i];
    float4 uv = ((const float4*)u)[i];
    float4 o;
    o.x = gv.x * (1.0f / (1.0f + __expf(-gv.x))) * uv.x;
    o.y = gv.y * (1.0f / (1.0f + __expf(-gv.y))) * uv.y;
    o.z = gv.z * (1.0f / (1.0f + __expf(-gv.z))) * uv.z;
    o.w = gv.w * (1.0f / (1.0f + __expf(-gv.w))) * uv.w;
    ((float4*)out)[i] = o;
}

// ---------------------------------------------------------------------------
// Launch sequence
// ---------------------------------------------------------------------------
extern "C" void kernel_launch(void* const* d_in, const int* in_sizes, int n_in,
                              void* d_out, int out_size)
{
    (void)in_sizes; (void)n_in; (void)out_size;

    const float* hidden   = (const float*)d_in[0];
    const float* context  = (const float*)d_in[1];
    const float* sa_norm  = (const float*)d_in[2];
    const float* sa_wq    = (const float*)d_in[3];
    const float* sa_wk    = (const float*)d_in[4];
    const float* sa_wv    = (const float*)d_in[5];
    const float* sa_wo    = (const float*)d_in[6];
    const float* ca_norm  = (const float*)d_in[7];
    const float* ca_wq    = (const float*)d_in[8];
    const float* ca_wk    = (const float*)d_in[9];
    const float* ca_wv    = (const float*)d_in[10];
    const float* ca_wo    = (const float*)d_in[11];
    const float* mlp_norm = (const float*)d_in[12];
    const float* w_gate   = (const float*)d_in[13];
    const float* w_up     = (const float*)d_in[14];
    const float* w_down   = (const float*)d_in[15];
    float* out = (float*)d_out;

    float *xn, *q, *k, *v, *att, *h1, *h2, *gate, *up, *gu;
    cudaGetSymbolAddress((void**)&xn,   g_xn);
    cudaGetSymbolAddress((void**)&q,    g_q);
    cudaGetSymbolAddress((void**)&k,    g_k);
    cudaGetSymbolAddress((void**)&v,    g_v);
    cudaGetSymbolAddress((void**)&att,  g_att);
    cudaGetSymbolAddress((void**)&h1,   g_h1);
    cudaGetSymbolAddress((void**)&h2,   g_h2);
    cudaGetSymbolAddress((void**)&gate, g_gate);
    cudaGetSymbolAddress((void**)&up,   g_up);
    cudaGetSymbolAddress((void**)&gu,   g_gu);

    cudaFuncSetAttribute(attn_tc_kernel,
                         cudaFuncAttributeMaxDynamicSharedMemorySize, ATT_SMEM);

    const dim3 blk(256);
    const dim3 gQKV(HDIM / 128, SQ / 128, 3);   // fused q,k,v
    const dim3 gO  (HDIM / 128, SQ / 128, 1);
    const dim3 gGU (ISZ  / 128, SQ / 128, 2);   // fused gate,up
    const dim3 gatt(SQ / 128, NH);

    // ---- Self-attention ----
    rmsnorm_kernel<<<SQ, blk>>>(hidden, sa_norm, xn);
    gemm_tf32_kernel<<<gQKV, blk>>>(xn, sa_wq, sa_wk, sa_wv, nullptr,
                                    q, k, v, SQ, HDIM, HDIM);
    attn_tc_kernel<<<gatt, blk, ATT_SMEM>>>(q, k, v, att);
    gemm_tf32_kernel<<<gO, blk>>>(att, sa_wo, sa_wo, sa_wo, hidden,
                                  h1, h1, h1, SQ, HDIM, HDIM);

    // ---- Cross-attention ----
    rmsnorm_kernel<<<SQ, blk>>>(h1, ca_norm, xn);
    gemm_tf32_kernel<<<gO, blk>>>(xn, ca_wq, ca_wq, ca_wq, nullptr,
                                  q, q, q, SQ, HDIM, HDIM);
    gemm_tf32_kernel<<<dim3(HDIM / 128, SQ / 128, 2), blk>>>(
        context, ca_wk, ca_wv, ca_wv, nullptr,
        k, v, v, SQ, HDIM, HDIM);
    attn_tc_kernel<<<gatt, blk, ATT_SMEM>>>(q, k, v, att);
    gemm_tf32_kernel<<<gO, blk>>>(att, ca_wo, ca_wo, ca_wo, h1,
                                  h2, h2, h2, SQ, HDIM, HDIM);

    // ---- MLP ----
    rmsnorm_kernel<<<SQ, blk>>>(h2, mlp_norm, xn);
    gemm_tf32_kernel<<<gGU, blk>>>(xn, w_gate, w_up, w_up, nullptr,
                                   gate, up, up, SQ, ISZ, HDIM);
    silu_mul_kernel<<<(SQ * ISZ / 4 + 255) / 256, blk>>>(gate, up, gu,
                                                         SQ * ISZ / 4);
    gemm_tf32_kernel<<<gO, blk>>>(gu, w_down, w_down, w_down, h2,
                                  out, out, out, SQ, HDIM, ISZ);
}